// round 2
// baseline (speedup 1.0000x reference)
#include <cuda_runtime.h>
#include <cuda_bf16.h>

// Path signature, truncation level 4.
// path: (B=128, S=512, D=8) fp32 -> out: (B, 8+64+512+4096=4680) fp32
//
// One CTA per batch element, 512 threads; thread m owns multi-index
// (i,j,k) = (m>>6, (m>>3)&7, m&7) and the 8 level-4 entries s4[i,j,k,0..7],
// the level-3 entry s3[i,j,k], plus redundant private copies of s2[i,j]
// and s1[i]. All state lives in registers; increments live in shared memory.
// No per-step synchronization at all.

#define SD 512         // sequence length
#define DD 8           // path dimension
#define TT (SD - 1)    // 511 increments
#define OUT_PER_B (DD + DD*DD + DD*DD*DD + DD*DD*DD*DD)  // 4680

__global__ __launch_bounds__(512, 1)
void signature_kernel(const float* __restrict__ path, float* __restrict__ out)
{
    __shared__ __align__(16) float inc[TT * DD];   // 16352 bytes

    const int b = blockIdx.x;
    const int m = threadIdx.x;                      // 0..511
    const float* p = path + (size_t)b * SD * DD;

    // Build segment increments into shared memory (coalesced float4 loads).
    for (int t = m; t < TT; t += 512) {
        const float4 a0 = *(const float4*)(p + t * DD);
        const float4 a1 = *(const float4*)(p + t * DD + 4);
        const float4 c0 = *(const float4*)(p + (t + 1) * DD);
        const float4 c1 = *(const float4*)(p + (t + 1) * DD + 4);
        float4* o = (float4*)(inc + t * DD);
        o[0] = make_float4(c0.x - a0.x, c0.y - a0.y, c0.z - a0.z, c0.w - a0.w);
        o[1] = make_float4(c1.x - a1.x, c1.y - a1.y, c1.z - a1.z, c1.w - a1.w);
    }
    __syncthreads();

    const int i = m >> 6;
    const int j = (m >> 3) & 7;
    const int k = m & 7;

    float s1 = 0.f;        // s1[i]   (replicated across 64 threads)
    float s2 = 0.f;        // s2[i,j] (replicated across 8 threads)
    float s3 = 0.f;        // s3[i,j,k]
    float s4[8];
    #pragma unroll
    for (int l = 0; l < 8; ++l) s4[l] = 0.f;

    const float* __restrict__ ri = inc + i;   // stride DD per step
    const float* __restrict__ rj = inc + j;
    const float* __restrict__ rk = inc + k;

    #pragma unroll 4
    for (int t = 0; t < TT; ++t) {
        const float* row = inc + t * DD;
        const float4 v0 = *(const float4*)(row);
        const float4 v1 = *(const float4*)(row + 4);
        const float dxi = ri[t * DD];
        const float dxj = rj[t * DD];
        const float dxk = rk[t * DD];

        const float h = dxj * dxk;

        // Level-4 coefficient: c = h*(dxi/24 + s1/6) + 0.5*s2*dxk + s3
        float c = fmaf(h, fmaf(s1, (1.f/6.f), dxi * (1.f/24.f)), s3);
        c = fmaf(s2 * 0.5f, dxk, c);

        // s4[i,j,k,l] += dx[l] * c   (rank-1 update, old s1/s2/s3 used)
        s4[0] = fmaf(v0.x, c, s4[0]);
        s4[1] = fmaf(v0.y, c, s4[1]);
        s4[2] = fmaf(v0.z, c, s4[2]);
        s4[3] = fmaf(v0.w, c, s4[3]);
        s4[4] = fmaf(v1.x, c, s4[4]);
        s4[5] = fmaf(v1.y, c, s4[5]);
        s4[6] = fmaf(v1.z, c, s4[6]);
        s4[7] = fmaf(v1.w, c, s4[7]);

        // s3 += h*(dxi/6 + s1/2) + s2*dxk   (old s1, s2)
        const float g = fmaf(s1, 0.5f, dxi * (1.f/6.f));
        s3 = fmaf(h, g, s3);
        s3 = fmaf(s2, dxk, s3);

        // s2 += dxj*(dxi/2 + s1)            (old s1)
        s2 = fmaf(dxj, fmaf(dxi, 0.5f, s1), s2);

        // s1 += dxi
        s1 += dxi;
    }

    // Emit results: out layout per batch = [s1(8) | s2(64) | s3(512) | s4(4096)]
    float* ob = out + (size_t)b * OUT_PER_B;

    float4* o4 = (float4*)(ob + DD + DD*DD + DD*DD*DD + m * 8);
    o4[0] = make_float4(s4[0], s4[1], s4[2], s4[3]);
    o4[1] = make_float4(s4[4], s4[5], s4[6], s4[7]);

    ob[DD + DD*DD + m] = s3;

    if (k == 0)        ob[DD + (m >> 3)] = s2;   // i*8 + j
    if ((m & 63) == 0) ob[m >> 6]        = s1;   // i
}

extern "C" void kernel_launch(void* const* d_in, const int* in_sizes, int n_in,
                              void* d_out, int out_size)
{
    const float* path = (const float*)d_in[0];
    float* out = (float*)d_out;
    const int nb = in_sizes[0] / (SD * DD);   // 128
    signature_kernel<<<nb, 512>>>(path, out);
}

// round 3
// speedup vs baseline: 1.2063x; 1.2063x over previous
#include <cuda_runtime.h>
#include <cuda_bf16.h>

// Path signature, truncation level 4.
// path: (B=128, S=512, D=8) fp32 -> out: (B, 8+64+512+4096=4680) fp32
//
// One CTA per batch, 1024 threads = two time-halves (Chen associativity):
//   half h (tid>>9) computes the signature of steps [256h, 256h+256) with
//   thread m = tid&511 owning (i,j,k) = (m>>6,(m>>3)&7,m&7).
// Final signature = sigA (x) sigB  (truncated tensor product, one-off).
//
// Per step, thread m does a rank-1 level-4 update s4[l] += dx[l]*c using
// packed fma.rn.f32x2 (4 FFMA2), plus ~12 scalar ops for the s1/s2/s3/c
// recursion. dxi/dxj/dxk come from a TRANSPOSED smem table (1 LDS.128 per
// 4 steps per stream); the full dx row comes from a row-major table
// (2 LDS.128/step). No per-step synchronization.

#define SD 512
#define DD 8
#define HALF_T 256
#define TPAD 516                       // padded row stride of transposed table
#define OUT_PER_B (DD + DD*DD + DD*DD*DD + DD*DD*DD*DD)  // 4680

__device__ __forceinline__ void ffma2(unsigned long long& d,
                                      unsigned long long a,
                                      unsigned long long b) {
    asm("fma.rn.f32x2 %0, %1, %2, %0;" : "+l"(d) : "l"(a), "l"(b));
}

__global__ __launch_bounds__(1024, 1)
void signature_kernel(const float* __restrict__ path, float* __restrict__ out)
{
    // [0..4095]      inc row-major  (512 rows x 8)   -- aliased by combine bufs
    // [4096..8223]   incT transposed (8 x 516)
    __shared__ __align__(16) float sm[4096 + 8 * TPAD];

    const int b   = blockIdx.x;
    const int tid = threadIdx.x;
    const int half = tid >> 9;
    const int m    = tid & 511;
    const float* p = path + (size_t)b * SD * DD;

    // ---- Build both increment tables (row 511 zero-padded: exp(0)=identity).
    if (tid < 512) {
        const int t = tid;
        float r[8];
        if (t < 511) {
            const float4 a0 = *(const float4*)(p + t * DD);
            const float4 a1 = *(const float4*)(p + t * DD + 4);
            const float4 c0 = *(const float4*)(p + (t + 1) * DD);
            const float4 c1 = *(const float4*)(p + (t + 1) * DD + 4);
            r[0]=c0.x-a0.x; r[1]=c0.y-a0.y; r[2]=c0.z-a0.z; r[3]=c0.w-a0.w;
            r[4]=c1.x-a1.x; r[5]=c1.y-a1.y; r[6]=c1.z-a1.z; r[7]=c1.w-a1.w;
        } else {
            #pragma unroll
            for (int d = 0; d < 8; ++d) r[d] = 0.f;
        }
        *(float4*)(sm + t * DD)     = make_float4(r[0], r[1], r[2], r[3]);
        *(float4*)(sm + t * DD + 4) = make_float4(r[4], r[5], r[6], r[7]);
        #pragma unroll
        for (int d = 0; d < 8; ++d) sm[4096 + d * TPAD + t] = r[d];
    }
    __syncthreads();

    const int i = m >> 6;
    const int j = (m >> 3) & 7;
    const int k = m & 7;

    float s1 = 0.f, s2 = 0.f, s3 = 0.f;
    unsigned long long s40 = 0ull, s41 = 0ull, s42 = 0ull, s43 = 0ull;

    const float* __restrict__ vrow = sm + half * (HALF_T * DD);
    const float* __restrict__ pI = sm + 4096 + i * TPAD + half * HALF_T;
    const float* __restrict__ pJ = sm + 4096 + j * TPAD + half * HALF_T;
    const float* __restrict__ pK = sm + 4096 + k * TPAD + half * HALF_T;

#define STEP(DXI, DXJ, DXK, TT_) do {                                         \
    const ulonglong2 va = *(const ulonglong2*)(vrow + (TT_) * DD);            \
    const ulonglong2 vb = *(const ulonglong2*)(vrow + (TT_) * DD + 4);        \
    const float h  = (DXJ) * (DXK);                                           \
    const float t1 = (DXI) * (1.f/24.f);                                      \
    const float t2 = fmaf(s1, (1.f/6.f), t1);                                 \
    const float c0 = fmaf(h, t2, s3);                                         \
    const float u  = s2 * (DXK);                                              \
    const float c  = fmaf(u, 0.5f, c0);                                       \
    unsigned long long cc;                                                    \
    asm("mov.b64 %0, {%1, %1};" : "=l"(cc) : "f"(c));                         \
    ffma2(s40, va.x, cc);                                                     \
    ffma2(s41, va.y, cc);                                                     \
    ffma2(s42, vb.x, cc);                                                     \
    ffma2(s43, vb.y, cc);                                                     \
    const float g3 = fmaf(t2, 3.f, t1);  /* = s1/2 + dxi/6 */                 \
    s3 = fmaf(h, g3, s3 + u);                                                 \
    s2 = fmaf((DXJ), fmaf((DXI), 0.5f, s1), s2);                              \
    s1 += (DXI);                                                              \
} while (0)

    #pragma unroll 4
    for (int g = 0; g < HALF_T / 4; ++g) {
        const float4 di = *(const float4*)(pI + g * 4);
        const float4 dj = *(const float4*)(pJ + g * 4);
        const float4 dk = *(const float4*)(pK + g * 4);
        const int tb = g * 4;
        STEP(di.x, dj.x, dk.x, tb);
        STEP(di.y, dj.y, dk.y, tb + 1);
        STEP(di.z, dj.z, dk.z, tb + 2);
        STEP(di.w, dj.w, dk.w, tb + 3);
    }
#undef STEP

    // Unpack s4 register pairs.
    float a4[8];
    asm("mov.b64 {%0, %1}, %2;" : "=f"(a4[0]), "=f"(a4[1]) : "l"(s40));
    asm("mov.b64 {%0, %1}, %2;" : "=f"(a4[2]), "=f"(a4[3]) : "l"(s41));
    asm("mov.b64 {%0, %1}, %2;" : "=f"(a4[4]), "=f"(a4[5]) : "l"(s42));
    asm("mov.b64 {%0, %1}, %2;" : "=f"(a4[6]), "=f"(a4[7]) : "l"(s43));

    // ---- Combine: S = A (x) B (truncated Chen product). B = second half.
    float* b4 = sm;            // 4096 floats
    float* b3 = sm + 4096;     // 512
    float* b2 = sm + 4608;     // 64
    float* b1 = sm + 4672;     // 8   (all alias dead inc tables)

    __syncthreads();           // everyone done reading inc tables

    if (half == 1) {
        *(float4*)(b4 + m * 8)     = make_float4(a4[0], a4[1], a4[2], a4[3]);
        *(float4*)(b4 + m * 8 + 4) = make_float4(a4[4], a4[5], a4[6], a4[7]);
        b3[m] = s3;
        if (k == 0)        b2[m >> 3] = s2;
        if ((m & 63) == 0) b1[i]      = s1;
    }
    __syncthreads();

    if (half == 0) {
        // Load B pieces this thread needs.
        float bb1[8];
        #pragma unroll
        for (int l = 0; l < 8; ++l) bb1[l] = b1[l];
        const float4 q0 = *(const float4*)(b2 + k * 8);
        const float4 q1 = *(const float4*)(b2 + k * 8 + 4);
        const float b2kl[8] = {q0.x,q0.y,q0.z,q0.w,q1.x,q1.y,q1.z,q1.w};
        const float b2jk = b2[j * 8 + k];
        const float4 r0 = *(const float4*)(b3 + j * 64 + k * 8);
        const float4 r1 = *(const float4*)(b3 + j * 64 + k * 8 + 4);
        const float b3jkl[8] = {r0.x,r0.y,r0.z,r0.w,r1.x,r1.y,r1.z,r1.w};
        const float4 w0 = *(const float4*)(b4 + m * 8);
        const float4 w1 = *(const float4*)(b4 + m * 8 + 4);
        const float b4v[8] = {w0.x,w0.y,w0.z,w0.w,w1.x,w1.y,w1.z,w1.w};
        const float bb3m = b3[m];

        float r4[8];
        #pragma unroll
        for (int l = 0; l < 8; ++l) {
            float acc = a4[l] + b4v[l];
            acc = fmaf(s3, bb1[l],   acc);
            acc = fmaf(s2, b2kl[l],  acc);
            acc = fmaf(s1, b3jkl[l], acc);
            r4[l] = acc;
        }
        float r3 = s3 + bb3m;
        r3 = fmaf(s2, bb1[k], r3);
        r3 = fmaf(s1, b2jk,  r3);
        float r2 = s2 + b2[(m >> 3)];
        r2 = fmaf(s1, bb1[j], r2);
        const float r1s = s1 + bb1[i];

        // ---- Emit: [s1(8) | s2(64) | s3(512) | s4(4096)] per batch.
        float* ob = out + (size_t)b * OUT_PER_B;
        float4* o4 = (float4*)(ob + DD + DD*DD + DD*DD*DD + m * 8);
        o4[0] = make_float4(r4[0], r4[1], r4[2], r4[3]);
        o4[1] = make_float4(r4[4], r4[5], r4[6], r4[7]);
        ob[DD + DD*DD + m] = r3;
        if (k == 0)        ob[DD + (m >> 3)] = r2;
        if ((m & 63) == 0) ob[m >> 6]        = r1s;
    }
}

extern "C" void kernel_launch(void* const* d_in, const int* in_sizes, int n_in,
                              void* d_out, int out_size)
{
    const float* path = (const float*)d_in[0];
    float* out = (float*)d_out;
    const int nb = in_sizes[0] / (SD * DD);   // 128
    signature_kernel<<<nb, 1024>>>(path, out);
}

// round 6
// speedup vs baseline: 1.2242x; 1.0148x over previous
#include <cuda_runtime.h>
#include <cuda_bf16.h>

// Path signature, truncation level 4.
// path: (B=128, S=512, D=8) fp32 -> out: (B, 8+64+512+4096 = 4680) fp32
//
// One CTA per batch, 512 threads; thread m owns (i,j,k)=(m>>6,(m>>3)&7,m&7).
// The two TIME HALVES (steps 0..255 and 256..511, padded with one zero
// increment = identity) are run SIMULTANEOUSLY in the two lanes of packed
// f32x2 registers: every recursion op serves both halves. The increment
// tables are stored pair-interleaved ({half0, half1} float2), so the packed
// level-4 coefficient {cA,cB} feeds fma.rn.f32x2 rank-1 updates directly —
// no pack/unpack in the loop. Final signature = sigA (x) sigB via a one-off
// truncated Chen product through shared memory.

#define SD 512
#define DD 8
#define HT 256                 // steps per half
#define TRP_STRIDE 516         // floats per d-row of transposed pair table
#define OUT_PER_B (DD + DD*DD + DD*DD*DD + DD*DD*DD*DD)  // 4680

typedef unsigned long long u64;

__device__ __forceinline__ u64 dup2(float x) {
    u64 r; asm("mov.b64 %0, {%1, %1};" : "=l"(r) : "f"(x)); return r;
}
__device__ __forceinline__ u64 fmul2(u64 a, u64 b) {
    u64 r; asm("mul.rn.f32x2 %0, %1, %2;" : "=l"(r) : "l"(a), "l"(b)); return r;
}
__device__ __forceinline__ u64 fadd2(u64 a, u64 b) {
    u64 r; asm("add.rn.f32x2 %0, %1, %2;" : "=l"(r) : "l"(a), "l"(b)); return r;
}
__device__ __forceinline__ u64 ffma2(u64 a, u64 b, u64 c) {
    u64 r; asm("fma.rn.f32x2 %0, %1, %2, %3;" : "=l"(r) : "l"(a), "l"(b), "l"(c)); return r;
}
__device__ __forceinline__ void facc2(u64& d, u64 a, u64 b) {
    asm("fma.rn.f32x2 %0, %1, %2, %0;" : "+l"(d) : "l"(a), "l"(b));
}
__device__ __forceinline__ float lo2(u64 a) {
    float l, h; asm("mov.b64 {%0, %1}, %2;" : "=f"(l), "=f"(h) : "l"(a)); return l;
}
__device__ __forceinline__ float hi2(u64 a) {
    float l, h; asm("mov.b64 {%0, %1}, %2;" : "=f"(l), "=f"(h) : "l"(a)); return h;
}

__global__ __launch_bounds__(512, 1)
void signature_kernel(const float* __restrict__ path, float* __restrict__ out)
{
    // [0 .. 4095]            rowp: 256 x 8 float2  {half0, half1}  (16 KB)
    // [4096 .. 4096+8*516)   trp:  8 x 256 float2, padded stride   (16.5 KB)
    __shared__ __align__(16) float sm[4096 + DD * TRP_STRIDE];

    const int b = blockIdx.x;
    const int m = threadIdx.x;            // 0..511
    const float* p = path + (size_t)b * SD * DD;

    // ---- Build pair-interleaved increment tables. Thread t computes inc[t].
    {
        const int t = m;
        float r[8];
        if (t < SD - 1) {
            const float4 a0 = *(const float4*)(p + t * DD);
            const float4 a1 = *(const float4*)(p + t * DD + 4);
            const float4 c0 = *(const float4*)(p + (t + 1) * DD);
            const float4 c1 = *(const float4*)(p + (t + 1) * DD + 4);
            r[0]=c0.x-a0.x; r[1]=c0.y-a0.y; r[2]=c0.z-a0.z; r[3]=c0.w-a0.w;
            r[4]=c1.x-a1.x; r[5]=c1.y-a1.y; r[6]=c1.z-a1.z; r[7]=c1.w-a1.w;
        } else {
            #pragma unroll
            for (int d = 0; d < 8; ++d) r[d] = 0.f;   // pad: exp(0)=identity
        }
        const int tp = t & (HT - 1);      // pair-time
        const int sl = t >> 8;            // 0 = half A (lo), 1 = half B (hi)
        #pragma unroll
        for (int l = 0; l < 8; ++l) sm[tp * 16 + l * 2 + sl] = r[l];
        #pragma unroll
        for (int d = 0; d < 8; ++d) sm[4096 + d * TRP_STRIDE + tp * 2 + sl] = r[d];
    }
    __syncthreads();

    const int i = m >> 6;
    const int j = (m >> 3) & 7;
    const int k = m & 7;

    u64 s1 = 0ull, s2 = 0ull, s3 = 0ull;
    u64 s4[8];
    #pragma unroll
    for (int l = 0; l < 8; ++l) s4[l] = 0ull;

    const u64 C24 = dup2(1.f / 24.f);
    const u64 C6  = dup2(1.f / 6.f);
    const u64 CH  = dup2(0.5f);
    const u64 C3  = dup2(3.f);

    const float* __restrict__ rowb = sm;
    const float* __restrict__ pI = sm + 4096 + i * TRP_STRIDE;
    const float* __restrict__ pJ = sm + 4096 + j * TRP_STRIDE;
    const float* __restrict__ pK = sm + 4096 + k * TRP_STRIDE;

#define STEP(DI, DJ, DK, TP_) do {                                            \
    const ulonglong2 ra = *(const ulonglong2*)(rowb + (TP_) * 16);            \
    const ulonglong2 rb = *(const ulonglong2*)(rowb + (TP_) * 16 + 4);        \
    const ulonglong2 rc = *(const ulonglong2*)(rowb + (TP_) * 16 + 8);        \
    const ulonglong2 rd = *(const ulonglong2*)(rowb + (TP_) * 16 + 12);       \
    const u64 h  = fmul2((DJ), (DK));                                         \
    const u64 t1 = fmul2((DI), C24);                                          \
    const u64 t2 = ffma2(s1, C6, t1);                                         \
    const u64 c0 = ffma2(h, t2, s3);                                          \
    const u64 u  = fmul2(s2, (DK));                                           \
    const u64 c  = ffma2(u, CH, c0);                                          \
    facc2(s4[0], ra.x, c);                                                    \
    facc2(s4[1], ra.y, c);                                                    \
    facc2(s4[2], rb.x, c);                                                    \
    facc2(s4[3], rb.y, c);                                                    \
    facc2(s4[4], rc.x, c);                                                    \
    facc2(s4[5], rc.y, c);                                                    \
    facc2(s4[6], rd.x, c);                                                    \
    facc2(s4[7], rd.y, c);                                                    \
    const u64 g3 = ffma2(t2, C3, t1);   /* = s1/2 + dxi/6 */                  \
    s3 = ffma2(h, g3, fadd2(s3, u));                                          \
    s2 = ffma2((DJ), ffma2((DI), CH, s1), s2);                                \
    s1 = fadd2(s1, (DI));                                                     \
} while (0)

    #pragma unroll 2
    for (int g = 0; g < HT / 2; ++g) {
        // one LDS.128 per stream covers two pair-steps ({t}, {t+1} float2s)
        const ulonglong2 di = *(const ulonglong2*)(pI + g * 4);
        const ulonglong2 dj = *(const ulonglong2*)(pJ + g * 4);
        const ulonglong2 dk = *(const ulonglong2*)(pK + g * 4);
        STEP(di.x, dj.x, dk.x, 2 * g);
        STEP(di.y, dj.y, dk.y, 2 * g + 1);
    }
#undef STEP

    // ---- Split packed state: A = lo lanes (first half), B = hi lanes.
    float a4[8], b4v[8];
    #pragma unroll
    for (int l = 0; l < 8; ++l) { a4[l] = lo2(s4[l]); b4v[l] = hi2(s4[l]); }
    const float a1 = lo2(s1), a2 = lo2(s2), a3 = lo2(s3);
    const float bb1s = hi2(s1), bb2s = hi2(s2), bb3s = hi2(s3);

    // ---- Chen combine: S = A (x) B through shared memory (aliases tables).
    float* b4 = sm;            // 4096 floats
    float* b3 = sm + 4096;     // 512
    float* b2 = sm + 4608;     // 64
    float* b1 = sm + 4672;     // 8

    __syncthreads();           // done reading increment tables

    *(float4*)(b4 + m * 8)     = make_float4(b4v[0], b4v[1], b4v[2], b4v[3]);
    *(float4*)(b4 + m * 8 + 4) = make_float4(b4v[4], b4v[5], b4v[6], b4v[7]);
    b3[m] = bb3s;
    if (k == 0)        b2[m >> 3] = bb2s;
    if ((m & 63) == 0) b1[i]      = bb1s;
    __syncthreads();

    float bb1[8];
    #pragma unroll
    for (int l = 0; l < 8; ++l) bb1[l] = b1[l];
    const float4 q0 = *(const float4*)(b2 + k * 8);
    const float4 q1 = *(const float4*)(b2 + k * 8 + 4);
    const float b2kl[8] = {q0.x,q0.y,q0.z,q0.w,q1.x,q1.y,q1.z,q1.w};
    const float b2jk = b2[j * 8 + k];
    const float4 r0 = *(const float4*)(b3 + j * 64 + k * 8);
    const float4 r1 = *(const float4*)(b3 + j * 64 + k * 8 + 4);
    const float b3jkl[8] = {r0.x,r0.y,r0.z,r0.w,r1.x,r1.y,r1.z,r1.w};
    const float4 w0 = *(const float4*)(b4 + m * 8);
    const float4 w1 = *(const float4*)(b4 + m * 8 + 4);
    const float b4m[8] = {w0.x,w0.y,w0.z,w0.w,w1.x,w1.y,w1.z,w1.w};
    const float bb3m = b3[m];

    float r4[8];
    #pragma unroll
    for (int l = 0; l < 8; ++l) {
        float acc = a4[l] + b4m[l];
        acc = fmaf(a3, bb1[l],   acc);
        acc = fmaf(a2, b2kl[l],  acc);
        acc = fmaf(a1, b3jkl[l], acc);
        r4[l] = acc;
    }
    float r3 = a3 + bb3m;
    r3 = fmaf(a2, bb1[k], r3);
    r3 = fmaf(a1, b2jk,  r3);
    float r2 = a2 + b2[m >> 3];
    r2 = fmaf(a1, bb1[j], r2);
    const float r1s = a1 + bb1[i];

    // ---- Emit: [s1(8) | s2(64) | s3(512) | s4(4096)] per batch.
    float* ob = out + (size_t)b * OUT_PER_B;
    float4* o4 = (float4*)(ob + DD + DD*DD + DD*DD*DD + m * 8);
    o4[0] = make_float4(r4[0], r4[1], r4[2], r4[3]);
    o4[1] = make_float4(r4[4], r4[5], r4[6], r4[7]);
    ob[DD + DD*DD + m] = r3;
    if (k == 0)        ob[DD + (m >> 3)] = r2;
    if ((m & 63) == 0) ob[m >> 6]        = r1s;
}

extern "C" void kernel_launch(void* const* d_in, const int* in_sizes, int n_in,
                              void* d_out, int out_size)
{
    const float* path = (const float*)d_in[0];
    float* out = (float*)d_out;
    const int nb = in_sizes[0] / (SD * DD);   // 128
    signature_kernel<<<nb, 512>>>(path, out);
}